// round 15
// baseline (speedup 1.0000x reference)
#include <cuda_runtime.h>

#define T_STEPS 1024
#define N_AGENTS 128
#define R_RUNS 128
#define PF 3
#define NPHASE 1089   // 3*363 >= 1087; extra phases fully store-gated

typedef unsigned long long u64;

__device__ __forceinline__ float tanh_approx(float x) {
    float r;
    asm("tanh.approx.f32 %0, %1;" : "=f"(r) : "f"(x));
    return r;
}
__device__ __forceinline__ float ex2_approx(float x) {
    float r;
    asm("ex2.approx.f32 %0, %1;" : "=f"(r) : "f"(x));
    return r;
}
__device__ __forceinline__ float rcp_approx(float x) {
    float r;
    asm("rcp.approx.f32 %0, %1;" : "=f"(r) : "f"(x));
    return r;
}
__device__ __forceinline__ u64 pk(float lo, float hi) {
    u64 r;
    asm("mov.b64 %0, {%1, %2};" : "=l"(r) : "f"(lo), "f"(hi));
    return r;
}
__device__ __forceinline__ void upk(float& lo, float& hi, u64 v) {
    asm("mov.b64 {%0, %1}, %2;" : "=f"(lo), "=f"(hi) : "l"(v));
}
__device__ __forceinline__ u64 fma2(u64 a, u64 b, u64 c) {
    u64 d;
    asm("fma.rn.f32x2 %0, %1, %2, %3;" : "=l"(d) : "l"(a), "l"(b), "l"(c));
    return d;
}
// predicated vector store: no BSSY/BSYNC
__device__ __forceinline__ void st2_pred(float* p, unsigned t, float v0, float v1) {
    asm volatile("{\n\t.reg .pred q;\n\tsetp.lt.u32 q, %0, 1024;\n\t@q st.global.v2.f32 [%1], {%2, %3};\n\t}"
                 :: "r"(t), "l"(p), "f"(v0), "f"(v1) : "memory");
}
__device__ __forceinline__ void st2_pred_off(float* p, unsigned t, float v0, float v1) {
    asm volatile("{\n\t.reg .pred q;\n\tsetp.lt.u32 q, %0, 1024;\n\t@q st.global.v2.f32 [%1+-504], {%2, %3};\n\t}"
                 :: "r"(t), "l"(p), "f"(v0), "f"(v1) : "memory");
}

#define L1Y(Y, Q, A_, B_) do {                                                 \
    u64 aa_ = pk((A_), (A_)), bb_ = pk((B_), (B_));                            \
    _Pragma("unroll")                                                          \
    for (int j2 = 0; j2 < 5; ++j2) {                                           \
        u64 y2_ = fma2(U3p[j2], bb_, fma2(U2p[j2], aa_, (Q)[j2]));             \
        upk((Y)[2*j2], (Y)[2*j2+1], y2_);                                      \
    }                                                                          \
} while (0)

// R11's L2, unchanged: H is float[10] (units 0-5 sigmoid values, 6-9 tanh values)
#define L2(H, O0, O1, O2) do {                                                 \
    u64 s_[5];                                                                 \
    _Pragma("unroll")                                                          \
    for (int j2 = 0; j2 < 5; ++j2) s_[j2] = pk((H)[2*j2], (H)[2*j2+1]);        \
    u64 a0_ = fma2(V0p[0], s_[0], C20p);                                       \
    u64 a1_ = fma2(V1p[0], s_[0], C21p);                                       \
    u64 a2_ = fma2(V2p[0], s_[0], C22p);                                       \
    _Pragma("unroll")                                                          \
    for (int j2 = 1; j2 < 5; ++j2) {                                           \
        a0_ = fma2(V0p[j2], s_[j2], a0_);                                      \
        a1_ = fma2(V1p[j2], s_[j2], a1_);                                      \
        a2_ = fma2(V2p[j2], s_[j2], a2_);                                      \
    }                                                                          \
    float l0_, h0_, l1_, h1_, l2_, h2_;                                        \
    upk(l0_, h0_, a0_); upk(l1_, h1_, a1_); upk(l2_, h2_, a2_);                \
    (O0) = l0_ + h0_; (O1) = l1_ + h1_; (O2) = l2_ + h2_;                      \
} while (0)

#define MAKE_Q(Q, X0, X1) do {                                                 \
    u64 xx0_ = pk((X0), (X0)), xx1_ = pk((X1), (X1));                          \
    _Pragma("unroll")                                                          \
    for (int j2 = 0; j2 < 5; ++j2)                                             \
        (Q)[j2] = fma2(U1p[j2], xx1_, fma2(U0p[j2], xx0_, C1p[j2]));           \
} while (0)

// Hybrid activation replacing the 10-tanh burst:
// units 0-5: y prescaled by S=-2log2(e); s = 1/(1+2^y) via ex2 + paired rcp;
//            layer-2 cols 0-5 hold 2*W2, bias holds b2 - sum_{j<6} W2[:,j].
// units 6-9: plain tanh.
#define ACT10(H, Y) do {                                                       \
    float e0_ = ex2_approx((Y)[0]);                                            \
    float e1_ = ex2_approx((Y)[1]);                                            \
    float e2_ = ex2_approx((Y)[2]);                                            \
    float e3_ = ex2_approx((Y)[3]);                                            \
    float e4_ = ex2_approx((Y)[4]);                                            \
    float e5_ = ex2_approx((Y)[5]);                                            \
    (H)[6] = tanh_approx((Y)[6]);                                              \
    (H)[7] = tanh_approx((Y)[7]);                                              \
    (H)[8] = tanh_approx((Y)[8]);                                              \
    (H)[9] = tanh_approx((Y)[9]);                                              \
    float d0_ = e0_ + 1.0f, d1_ = e1_ + 1.0f;                                  \
    float d2_ = e2_ + 1.0f, d3_ = e3_ + 1.0f;                                  \
    float d4_ = e4_ + 1.0f, d5_ = e5_ + 1.0f;                                  \
    float r01_ = rcp_approx(d0_ * d1_);                                        \
    float r23_ = rcp_approx(d2_ * d3_);                                        \
    float r45_ = rcp_approx(d4_ * d5_);                                        \
    (H)[0] = d1_ * r01_; (H)[1] = d0_ * r01_;                                  \
    (H)[2] = d3_ * r23_; (H)[3] = d2_ * r23_;                                  \
    (H)[4] = d5_ * r45_; (H)[5] = d4_ * r45_;                                  \
} while (0)

// One phase with static queue slot I (0..2). Identical to R11 except ACT10.
#define PHASE_ITER(I) do {                                                     \
    const float aUp = __shfl_up_sync(0xffffffffu, o2B1, 1);                    \
    const float aA0 = (k == 0) ? 0.f : aUp;                                    \
    const float bA0 = (t0 >= 1) ? o1B0 : 0.f;                                  \
    const float aA1 = o2B0;                                                    \
    const float bA1 = (t0 >= 2) ? o1B1 : 0.f;                                  \
    const float4 h0 = xq0[I], h1 = xq1[I];                                     \
    const float4 n0 = *(const float4*)pf0;                                     \
    const float4 n1 = *(const float4*)pf1;                                     \
    xq0[I] = n0; xq1[I] = n1;                                                  \
    pf0 = ((unsigned)(t0 + PF) <= (T_STEPS - 2)) ? (pf0 + N_AGENTS * 2) : pf0; \
    pf1 = ((unsigned)(t0 - 1 + PF) <= (T_STEPS - 2)) ? (pf1 + N_AGENTS * 2) : pf1; \
    /* A-stage */                                                              \
    u64 qa0[5], qa1[5];                                                        \
    MAKE_Q(qa0, h0.x, h0.y);                                                   \
    MAKE_Q(qa1, h1.x, h1.y);                                                   \
    float yA0[10], yA1[10];                                                    \
    L1Y(yA0, qa0, aA0, bA0);                                                   \
    L1Y(yA1, qa1, aA1, bA1);                                                   \
    float hA0[10], hA1[10];                                                    \
    ACT10(hA0, yA0);                                                           \
    ACT10(hA1, yA1);                                                           \
    u64 qb0[5], qb1[5];                                                        \
    MAKE_Q(qb0, h0.z, h0.w);                                                   \
    MAKE_Q(qb1, h1.z, h1.w);                                                   \
    float o0A0, o1A0, o2A0, o0A1, o1A1, o2A1;                                  \
    L2(hA0, o0A0, o1A0, o2A0);                                                 \
    L2(hA1, o0A1, o1A1, o2A1);                                                 \
    const float bDn = __shfl_down_sync(0xffffffffu, o1A0, 1);                  \
    const float bB0 = (t0 >= 1) ? o1A1 : 0.f;                                  \
    const float bB1 = (t0 >= 2) ? ((k == 31) ? 0.f : bDn) : 0.f;               \
    /* B-stage */                                                              \
    float yB0[10], yB1[10];                                                    \
    L1Y(yB0, qb0, o2A0, bB0);                                                  \
    L1Y(yB1, qb1, o2A1, bB1);                                                  \
    float hB0[10], hB1[10];                                                    \
    ACT10(hB0, yB0);                                                           \
    ACT10(hB1, yB1);                                                           \
    float o0B0, n_o1B0, n_o2B0, o0B1, n_o1B1, n_o2B1;                          \
    L2(hB0, o0B0, n_o1B0, n_o2B0);                                             \
    L2(hB1, o0B1, n_o1B1, n_o2B1);                                             \
    o1B0 = n_o1B0; o2B0 = n_o2B0;                                              \
    o1B1 = n_o1B1; o2B1 = n_o2B1;                                              \
    st2_pred(optr, (unsigned)t0, o0A0, o0B0);                                  \
    st2_pred_off(optr, (unsigned)(t0 - 1), o0A1, o0B1);                        \
    optr += N_AGENTS;                                                          \
    ++t0;                                                                      \
} while (0)

__global__ __launch_bounds__(32, 1)
void com2net_hyb2(const float* __restrict__ runs,
                  const float* __restrict__ W1,
                  const float* __restrict__ b1,
                  const float* __restrict__ W2,
                  const float* __restrict__ b2,
                  float* __restrict__ out)
{
    const int k = threadIdx.x;   // lane owns pairs 2k (agents 4k,4k+1 @ t0) and 2k+1 (agents 4k+2,4k+3 @ t0-1)
    const int r = blockIdx.x;

    // ---- pack weights; hidden rows 0-5 sigmoid-form (prescale S), 6-9 tanh ----
    const float S = -2.8853900817779268f;   // -2*log2(e): tanh(z) = 2/(1+2^(S z)) - 1
    u64 U0p[5], U1p[5], U2p[5], U3p[5], C1p[5];
#pragma unroll
    for (int j2 = 0; j2 < 5; ++j2) {
        int j = 2 * j2;
        float sc = (j2 < 3) ? S : 1.0f;
        U0p[j2] = pk(W1[j*4+0] * sc, W1[(j+1)*4+0] * sc);
        U1p[j2] = pk(W1[j*4+1] * sc, W1[(j+1)*4+1] * sc);
        U2p[j2] = pk(W1[j*4+2] * sc, W1[(j+1)*4+2] * sc);
        U3p[j2] = pk(W1[j*4+3] * sc, W1[(j+1)*4+3] * sc);
        C1p[j2] = pk(b1[j] * sc,     b1[j+1] * sc);
    }
    u64 V0p[5], V1p[5], V2p[5], C20p, C21p, C22p;
    {
        float s0 = 0.f, s1 = 0.f, s2 = 0.f;
#pragma unroll
        for (int j = 0; j < 6; ++j) {
            s0 += W2[0*10 + j]; s1 += W2[1*10 + j]; s2 += W2[2*10 + j];
        }
#pragma unroll
        for (int j2 = 0; j2 < 5; ++j2) {
            int j = 2 * j2;
            float sc = (j2 < 3) ? 2.0f : 1.0f;
            V0p[j2] = pk(sc * W2[0*10+j], sc * W2[0*10+j+1]);
            V1p[j2] = pk(sc * W2[1*10+j], sc * W2[1*10+j+1]);
            V2p[j2] = pk(sc * W2[2*10+j], sc * W2[2*10+j+1]);
        }
        C20p = pk(b2[0] - s0, 0.f);
        C21p = pk(b2[1] - s1, 0.f);
        C22p = pk(b2[2] - s2, 0.f);
    }

    const float* xb0 = runs + (size_t)r * T_STEPS * N_AGENTS * 2 + (size_t)k * 8;
    const float* xb1 = xb0 + 4;

    float4 xq0[PF], xq1[PF];
#pragma unroll
    for (int d = 0; d < PF; ++d) {
        int t0c = d - 2 * k;       t0c = max(0, min(T_STEPS - 1, t0c));
        int t1c = d - 2 * k - 1;   t1c = max(0, min(T_STEPS - 1, t1c));
        xq0[d] = *(const float4*)(xb0 + (size_t)t0c * (N_AGENTS * 2));
        xq1[d] = *(const float4*)(xb1 + (size_t)t1c * (N_AGENTS * 2));
    }
    const float* pf0;
    const float* pf1;
    {
        int t0c = PF - 2 * k;       t0c = max(0, min(T_STEPS - 1, t0c));
        int t1c = PF - 2 * k - 1;   t1c = max(0, min(T_STEPS - 1, t1c));
        pf0 = xb0 + (size_t)t0c * (N_AGENTS * 2);
        pf1 = xb1 + (size_t)t1c * (N_AGENTS * 2);
    }

    float* optr = out + (size_t)r * T_STEPS * N_AGENTS + (size_t)4 * k
                      + (long long)(-2 * k) * N_AGENTS;
    int t0 = -2 * k;

    float o1B0 = 0.f, o2B0 = 0.f, o1B1 = 0.f, o2B1 = 0.f;

#pragma unroll 1
    for (int pb = 0; pb < NPHASE; pb += 3) {
        PHASE_ITER(0);
        PHASE_ITER(1);
        PHASE_ITER(2);
    }
}

extern "C" void kernel_launch(void* const* d_in, const int* in_sizes, int n_in,
                              void* d_out, int out_size)
{
    const float* runs = (const float*)d_in[0];
    const float* W1   = (const float*)d_in[1];
    const float* b1   = (const float*)d_in[2];
    const float* W2   = (const float*)d_in[3];
    const float* b2   = (const float*)d_in[4];
    float* out = (float*)d_out;
    com2net_hyb2<<<R_RUNS, 32>>>(runs, W1, b1, W2, b2, out);
}

// round 16
// speedup vs baseline: 1.4527x; 1.4527x over previous
#include <cuda_runtime.h>

#define T_STEPS 1024
#define N_AGENTS 128
#define R_RUNS 128
#define PF 3
#define NPHASE 1089   // 3*363 >= 1087 (max p = 1023 + 63); extras store-gated

typedef unsigned long long u64;

__device__ __forceinline__ float tanh_approx(float x) {
    float r;
    asm("tanh.approx.f32 %0, %1;" : "=f"(r) : "f"(x));
    return r;
}
__device__ __forceinline__ u64 pk(float lo, float hi) {
    u64 r;
    asm("mov.b64 %0, {%1, %2};" : "=l"(r) : "f"(lo), "f"(hi));
    return r;
}
__device__ __forceinline__ void upk(float& lo, float& hi, u64 v) {
    asm("mov.b64 {%0, %1}, %2;" : "=f"(lo), "=f"(hi) : "l"(v));
}
__device__ __forceinline__ u64 fma2(u64 a, u64 b, u64 c) {
    u64 d;
    asm("fma.rn.f32x2 %0, %1, %2, %3;" : "=l"(d) : "l"(a), "l"(b), "l"(c));
    return d;
}
// predicated global vector store: no BSSY/BSYNC
__device__ __forceinline__ void st2_pred(float* p, unsigned t, float v0, float v1) {
    asm volatile("{\n\t.reg .pred q;\n\tsetp.lt.u32 q, %0, 1024;\n\t@q st.global.v2.f32 [%1], {%2, %3};\n\t}"
                 :: "r"(t), "l"(p), "f"(v0), "f"(v1) : "memory");
}
// predicated shared scalar store: no BSSY/BSYNC
__device__ __forceinline__ void sts_pred(unsigned cond, unsigned saddr, float v) {
    asm volatile("{\n\t.reg .pred q;\n\tsetp.ne.u32 q, %0, 0;\n\t@q st.shared.f32 [%1], %2;\n\t}"
                 :: "r"(cond), "r"(saddr), "f"(v) : "memory");
}
__device__ __forceinline__ unsigned smem_u32(const void* p) {
    unsigned a;
    asm("{ .reg .u64 t; cvta.to.shared.u64 t, %1; cvt.u32.u64 %0, t; }" : "=r"(a) : "l"(p));
    return a;
}

#define L1Y(Y, Q, A_, B_) do {                                                 \
    u64 aa_ = pk((A_), (A_)), bb_ = pk((B_), (B_));                            \
    _Pragma("unroll")                                                          \
    for (int j2 = 0; j2 < 5; ++j2) {                                           \
        u64 y2_ = fma2(U3p[j2], bb_, fma2(U2p[j2], aa_, (Q)[j2]));             \
        upk((Y)[2*j2], (Y)[2*j2+1], y2_);                                      \
    }                                                                          \
} while (0)

#define L2(H, O0, O1, O2) do {                                                 \
    u64 s_[5];                                                                 \
    _Pragma("unroll")                                                          \
    for (int j2 = 0; j2 < 5; ++j2) s_[j2] = pk((H)[2*j2], (H)[2*j2+1]);        \
    u64 a0_ = fma2(V0p[0], s_[0], C20p);                                       \
    u64 a1_ = fma2(V1p[0], s_[0], C21p);                                       \
    u64 a2_ = fma2(V2p[0], s_[0], C22p);                                       \
    _Pragma("unroll")                                                          \
    for (int j2 = 1; j2 < 5; ++j2) {                                           \
        a0_ = fma2(V0p[j2], s_[j2], a0_);                                      \
        a1_ = fma2(V1p[j2], s_[j2], a1_);                                      \
        a2_ = fma2(V2p[j2], s_[j2], a2_);                                      \
    }                                                                          \
    float l0_, h0_, l1_, h1_, l2_, h2_;                                        \
    upk(l0_, h0_, a0_); upk(l1_, h1_, a1_); upk(l2_, h2_, a2_);                \
    (O0) = l0_ + h0_; (O1) = l1_ + h1_; (O2) = l2_ + h2_;                      \
} while (0)

#define MAKE_Q(Q, X0, X1) do {                                                 \
    u64 xx0_ = pk((X0), (X0)), xx1_ = pk((X1), (X1));                          \
    _Pragma("unroll")                                                          \
    for (int j2 = 0; j2 < 5; ++j2)                                             \
        (Q)[j2] = fma2(U1p[j2], xx1_, fma2(U0p[j2], xx0_, C1p[j2]));           \
} while (0)

// One phase, static queue slot I. Lane (tid 0..63) owns pair j = tid
// (agents 2j, 2j+1) at t = p - j.
// A(j): a = B(j-1).o2 prev phase (shfl_up; j==0 -> 0; j==32 -> smem slot2)
//       b = own B(j).o1 prev phase, gated t>=1
// B(j): a = own A(j).o2 this phase
//       b = A(j+1).o1 this phase (shfl_down; j==31 -> smem slot1; j==63 -> 0),
//           gated t>=1
#define PHASE_ITER(I) do {                                                     \
    const float bA = (t >= 1) ? o1B : 0.f;                                     \
    const float4 h = xq[I];                                                    \
    const float4 n = *(const float4*)pf;                                       \
    xq[I] = n;                                                                 \
    pf = ((unsigned)(t + PF) <= (T_STEPS - 2)) ? (pf + N_AGENTS * 2) : pf;     \
    u64 qa[5], qb[5];                                                          \
    MAKE_Q(qa, h.x, h.y);                                                      \
    MAKE_Q(qb, h.z, h.w);                                                      \
    float yA[10], hA[10];                                                      \
    L1Y(yA, qa, aSel, bA);                                                     \
    _Pragma("unroll")                                                          \
    for (int j = 0; j < 10; ++j) hA[j] = tanh_approx(yA[j]);                   \
    float o0A, o1A, o2A;                                                       \
    L2(hA, o0A, o1A, o2A);                                                     \
    sts_pred(is32, s1a, o1A);          /* pair32 publishes A.o1 for pair31 */  \
    const float bDn = __shfl_down_sync(0xffffffffu, o1A, 1);                   \
    __syncthreads();                   /* bar#1: slot1 visible */              \
    const float s1v = *sl1p;                                                   \
    float bB = (tid == 31) ? s1v : bDn;                                        \
    bB = (tid == 63) ? 0.f : bB;                                               \
    bB = (t >= 1) ? bB : 0.f;                                                  \
    float yB[10], hB[10];                                                      \
    L1Y(yB, qb, o2A, bB);                                                      \
    _Pragma("unroll")                                                          \
    for (int j = 0; j < 10; ++j) hB[j] = tanh_approx(yB[j]);                   \
    float o0B, n1_, n2_;                                                       \
    L2(hB, o0B, n1_, n2_);                                                     \
    o1B = n1_;                                                                 \
    sts_pred(is31, s2a, n2_);          /* pair31 publishes B.o2 for pair32 */  \
    __syncthreads();                   /* bar#2: slot2 visible for next phase */ \
    const float aUp = __shfl_up_sync(0xffffffffu, n2_, 1);                     \
    const float s2v = *sl2p;                                                   \
    aSel = (tid == 0) ? 0.f : aUp;                                             \
    aSel = (tid == 32) ? s2v : aSel;                                           \
    st2_pred(optr, (unsigned)t, o0A, o0B);                                     \
    optr += N_AGENTS;                                                          \
    ++t;                                                                       \
} while (0)

__global__ __launch_bounds__(64, 1)
void com2net_2wbar(const float* __restrict__ runs,
                   const float* __restrict__ W1,
                   const float* __restrict__ b1,
                   const float* __restrict__ W2,
                   const float* __restrict__ b2,
                   float* __restrict__ out)
{
    const int tid = threadIdx.x;   // pair j = tid, agents 2j, 2j+1
    const int r   = blockIdx.x;

    __shared__ float sl1, sl2;     // boundary scalars (pair32.A.o1 / pair31.B.o2)
    if (tid == 0) { sl1 = 0.f; sl2 = 0.f; }

    const unsigned s1a = smem_u32(&sl1);
    const unsigned s2a = smem_u32(&sl2);
    const float* sl1p = &sl1;
    const float* sl2p = &sl2;
    const unsigned is31 = (tid == 31) ? 1u : 0u;
    const unsigned is32 = (tid == 32) ? 1u : 0u;

    // ---- pack weights over hidden-unit pairs ----
    u64 U0p[5], U1p[5], U2p[5], U3p[5], C1p[5];
#pragma unroll
    for (int j2 = 0; j2 < 5; ++j2) {
        int j = 2 * j2;
        U0p[j2] = pk(W1[j*4+0], W1[(j+1)*4+0]);
        U1p[j2] = pk(W1[j*4+1], W1[(j+1)*4+1]);
        U2p[j2] = pk(W1[j*4+2], W1[(j+1)*4+2]);
        U3p[j2] = pk(W1[j*4+3], W1[(j+1)*4+3]);
        C1p[j2] = pk(b1[j],     b1[j+1]);
    }
    u64 V0p[5], V1p[5], V2p[5], C20p, C21p, C22p;
#pragma unroll
    for (int j2 = 0; j2 < 5; ++j2) {
        int j = 2 * j2;
        V0p[j2] = pk(W2[0*10+j], W2[0*10+j+1]);
        V1p[j2] = pk(W2[1*10+j], W2[1*10+j+1]);
        V2p[j2] = pk(W2[2*10+j], W2[2*10+j+1]);
    }
    C20p = pk(b2[0], 0.f);
    C21p = pk(b2[1], 0.f);
    C22p = pk(b2[2], 0.f);

    // x for pair j at t: 4 floats at runs[r][t][4j]
    const float* xb = runs + (size_t)r * T_STEPS * N_AGENTS * 2 + (size_t)tid * 4;

    float4 xq[PF];
#pragma unroll
    for (int d = 0; d < PF; ++d) {
        int tc = d - tid;
        tc = max(0, min(T_STEPS - 1, tc));
        xq[d] = *(const float4*)(xb + (size_t)tc * (N_AGENTS * 2));
    }
    const float* pf;
    {
        int tc = PF - tid;
        tc = max(0, min(T_STEPS - 1, tc));
        pf = xb + (size_t)tc * (N_AGENTS * 2);
    }

    // output: controls at out[r][t][2j], float2; running pointer, store predicated
    float* optr = out + (size_t)r * T_STEPS * N_AGENTS + (size_t)2 * tid
                      + (long long)(-tid) * N_AGENTS;
    int t = -tid;

    float o1B = 0.f;    // own B.o1 from prev phase
    float aSel = 0.f;   // resolved a-input for A (pre-shuffled / slot / zero)

    __syncthreads();    // smem slots initialized

#pragma unroll 1
    for (int pb = 0; pb < NPHASE; pb += 3) {
        PHASE_ITER(0);
        PHASE_ITER(1);
        PHASE_ITER(2);
    }
}

extern "C" void kernel_launch(void* const* d_in, const int* in_sizes, int n_in,
                              void* d_out, int out_size)
{
    const float* runs = (const float*)d_in[0];
    const float* W1   = (const float*)d_in[1];
    const float* b1   = (const float*)d_in[2];
    const float* W2   = (const float*)d_in[3];
    const float* b2   = (const float*)d_in[4];
    float* out = (float*)d_out;
    com2net_2wbar<<<R_RUNS, 64>>>(runs, W1, b1, W2, b2, out);
}

// round 17
// speedup vs baseline: 1.4654x; 1.0088x over previous
#include <cuda_runtime.h>

#define T_STEPS 1024
#define N_AGENTS 128
#define R_RUNS 128
#define PF 3
#define NPHASE 1089   // 3*363 >= 1087 (max p = 1023 + 63); extras store-gated

typedef unsigned long long u64;

__device__ __forceinline__ float tanh_approx(float x) {
    float r;
    asm("tanh.approx.f32 %0, %1;" : "=f"(r) : "f"(x));
    return r;
}
__device__ __forceinline__ u64 pk(float lo, float hi) {
    u64 r;
    asm("mov.b64 %0, {%1, %2};" : "=l"(r) : "f"(lo), "f"(hi));
    return r;
}
__device__ __forceinline__ void upk(float& lo, float& hi, u64 v) {
    asm("mov.b64 {%0, %1}, %2;" : "=f"(lo), "=f"(hi) : "l"(v));
}
__device__ __forceinline__ u64 fma2(u64 a, u64 b, u64 c) {
    u64 d;
    asm("fma.rn.f32x2 %0, %1, %2, %3;" : "=l"(d) : "l"(a), "l"(b), "l"(c));
    return d;
}
// predicated global vector store: no BSSY/BSYNC (cond: tcode < 1024)
__device__ __forceinline__ void st2_pred(float* p, unsigned tcode, float v0, float v1) {
    asm volatile("{\n\t.reg .pred q;\n\tsetp.lt.u32 q, %0, 1024;\n\t@q st.global.v2.f32 [%1], {%2, %3};\n\t}"
                 :: "r"(tcode), "l"(p), "f"(v0), "f"(v1) : "memory");
}
// predicated shared scalar store: no BSSY/BSYNC
__device__ __forceinline__ void sts_pred(unsigned cond, unsigned saddr, float v) {
    asm volatile("{\n\t.reg .pred q;\n\tsetp.ne.u32 q, %0, 0;\n\t@q st.shared.f32 [%1], %2;\n\t}"
                 :: "r"(cond), "r"(saddr), "f"(v) : "memory");
}
__device__ __forceinline__ unsigned smem_u32(const void* p) {
    unsigned a;
    asm("{ .reg .u64 t; cvta.to.shared.u64 t, %1; cvt.u32.u64 %0, t; }" : "=r"(a) : "l"(p));
    return a;
}

// x-partials for this lane's 5 hidden units (2 packed pairs + 1 scalar)
#define MAKE_Q5(Q01, Q23, Q4, X0, X1) do {                                     \
    u64 xx0_ = pk((X0), (X0)), xx1_ = pk((X1), (X1));                          \
    (Q01) = fma2(U1p0, xx1_, fma2(U0p0, xx0_, C1p0));                          \
    (Q23) = fma2(U1p1, xx1_, fma2(U0p1, xx0_, C1p1));                          \
    (Q4)  = fmaf(u1s, (X1), fmaf(u0s, (X0), c1s));                             \
} while (0)

// Half-MLP (5 hidden units) + cross-lane combine: both lanes end with FULL o0/o1/o2.
#define MLP5(O0, O1, O2, Q01, Q23, Q4, A_, B_) do {                            \
    u64 aa_ = pk((A_), (A_)), bb_ = pk((B_), (B_));                            \
    u64 y01_ = fma2(U3p0, bb_, fma2(U2p0, aa_, (Q01)));                        \
    u64 y23_ = fma2(U3p1, bb_, fma2(U2p1, aa_, (Q23)));                        \
    float y4_ = fmaf(u3s, (B_), fmaf(u2s, (A_), (Q4)));                        \
    float ya_, yb_, yc_, yd_;                                                  \
    upk(ya_, yb_, y01_); upk(yc_, yd_, y23_);                                  \
    float h0_ = tanh_approx(ya_);                                              \
    float h1_ = tanh_approx(yb_);                                              \
    float h2_ = tanh_approx(yc_);                                              \
    float h3_ = tanh_approx(yd_);                                              \
    float h4_ = tanh_approx(y4_);                                              \
    u64 s01_ = pk(h0_, h1_), s23_ = pk(h2_, h3_);                              \
    u64 a0_ = fma2(V0p0, s01_, fma2(V0p1, s23_, (u64)0));                      \
    u64 a1_ = fma2(V1p0, s01_, fma2(V1p1, s23_, (u64)0));                      \
    u64 a2_ = fma2(V2p0, s01_, fma2(V2p1, s23_, (u64)0));                      \
    float l0_, g0_, l1_, g1_, l2_, g2_;                                        \
    upk(l0_, g0_, a0_); upk(l1_, g1_, a1_); upk(l2_, g2_, a2_);                \
    float p0_ = fmaf(v0s, h4_, l0_ + g0_) + c20h;                              \
    float p1_ = fmaf(v1s, h4_, l1_ + g1_) + c21h;                              \
    float p2_ = fmaf(v2s, h4_, l2_ + g2_) + c22h;                              \
    (O0) = p0_ + __shfl_xor_sync(0xffffffffu, p0_, 1);                         \
    (O1) = p1_ + __shfl_xor_sync(0xffffffffu, p1_, 1);                         \
    (O2) = p2_ + __shfl_xor_sync(0xffffffffu, p2_, 1);                         \
} while (0)

// One phase, static queue slot I.
// 128 threads: warp w (0..3) owns pairs 16w..16w+15; lane = 2m+h, pair m, half h.
// Global pair jg = 16w + m owns agents 2jg, 2jg+1 at t = p - jg.
// A a-input: B(jg-1).o2 prev phase (shfl_up 2; m==0 -> slot s2 / zero).
// A b-input: own B.o1 prev phase, gated t>=1.
// B a-input: own A.o2 this phase (lane-local, full after xor-reduce).
// B b-input: A(jg+1).o1 this phase (shfl_down 2; m==15 -> slot s1 / zero), gated t>=1.
#define PHASE_ITER(I) do {                                                     \
    const float bA = (t >= 1) ? o1Bp : 0.f;                                    \
    const float4 hx = xq[I];                                                   \
    const float4 n = *(const float4*)pf;                                       \
    xq[I] = n;                                                                 \
    pf = ((unsigned)(t + PF) <= (T_STEPS - 2)) ? (pf + N_AGENTS * 2) : pf;     \
    u64 qa01, qa23, qb01, qb23; float qa4, qb4;                                \
    MAKE_Q5(qa01, qa23, qa4, hx.x, hx.y);                                      \
    MAKE_Q5(qb01, qb23, qb4, hx.z, hx.w);                                      \
    float o0A, o1A, o2A;                                                       \
    MLP5(o0A, o1A, o2A, qa01, qa23, qa4, aSel, bA);                            \
    sts_pred(wr1, s1wa, o1A);        /* warp>0, lane0: publish A(16w).o1 */    \
    const float bDn = __shfl_down_sync(0xffffffffu, o1A, 2);                   \
    __syncthreads();                 /* bar#1: s1 visible */                   \
    float bB = (m == 15) ? *s1rd : bDn;                                        \
    bB = (t >= 1) ? bB : 0.f;                                                  \
    float o0B, o1B, o2B;                                                       \
    MLP5(o0B, o1B, o2B, qb01, qb23, qb4, o2A, bB);                             \
    o1Bp = o1B;                                                                \
    sts_pred(wr2, s2wa, o2B);        /* warp<3, lane30: publish B(16w+15).o2 */\
    __syncthreads();                 /* bar#2: s2 visible for next phase */    \
    const float aUp = __shfl_up_sync(0xffffffffu, o2B, 2);                     \
    aSel = (m == 0) ? *s2rd : aUp;                                             \
    st2_pred(optr, (unsigned)t | hMask, o0A, o0B);                             \
    optr += N_AGENTS;                                                          \
    ++t;                                                                       \
} while (0)

__global__ __launch_bounds__(128, 1)
void com2net_4wsplit(const float* __restrict__ runs,
                     const float* __restrict__ W1,
                     const float* __restrict__ b1,
                     const float* __restrict__ W2,
                     const float* __restrict__ b2,
                     float* __restrict__ out)
{
    const int tid  = threadIdx.x;
    const int warp = tid >> 5;
    const int lane = tid & 31;
    const int m    = lane >> 1;          // pair within warp (0..15)
    const int h    = lane & 1;           // hidden-unit half (0: units 0-4, 1: 5-9)
    const int jg   = warp * 16 + m;      // global pair (0..63)
    const int r    = blockIdx.x;

    // smem slots: [0..2]=s1 (A.o1 fwd at boundaries), [3]=zero,
    //             [4..6]=s2 (B.o2 up at boundaries), [7]=zero
    __shared__ float slots[8];
    if (tid < 8) slots[tid] = 0.f;

    const float* s1rd = (warp < 3) ? &slots[warp] : &slots[3];
    const float* s2rd = (warp > 0) ? &slots[3 + warp] : &slots[7];
    const unsigned s1wa = smem_u32(&slots[(warp > 0) ? (warp - 1) : 0]);
    const unsigned s2wa = smem_u32(&slots[4 + ((warp < 3) ? warp : 2)]);
    const unsigned wr1 = (lane == 0 && warp > 0) ? 1u : 0u;
    const unsigned wr2 = (lane == 30 && warp < 3) ? 1u : 0u;
    const unsigned hMask = h ? 0x80000000u : 0u;

    // ---- this lane's 5 hidden-unit weight rows (units 5h .. 5h+4) ----
    const int u0i = 5 * h;
    u64 U0p0, U0p1, U1p0, U1p1, U2p0, U2p1, U3p0, U3p1, C1p0, C1p1;
    {
        int ja = u0i, jb = u0i + 2;
        U0p0 = pk(W1[ja*4+0], W1[(ja+1)*4+0]);  U0p1 = pk(W1[jb*4+0], W1[(jb+1)*4+0]);
        U1p0 = pk(W1[ja*4+1], W1[(ja+1)*4+1]);  U1p1 = pk(W1[jb*4+1], W1[(jb+1)*4+1]);
        U2p0 = pk(W1[ja*4+2], W1[(ja+1)*4+2]);  U2p1 = pk(W1[jb*4+2], W1[(jb+1)*4+2]);
        U3p0 = pk(W1[ja*4+3], W1[(ja+1)*4+3]);  U3p1 = pk(W1[jb*4+3], W1[(jb+1)*4+3]);
        C1p0 = pk(b1[ja], b1[ja+1]);            C1p1 = pk(b1[jb], b1[jb+1]);
    }
    const int j4 = u0i + 4;
    const float u0s = W1[j4*4+0], u1s = W1[j4*4+1], u2s = W1[j4*4+2], u3s = W1[j4*4+3];
    const float c1s = b1[j4];

    u64 V0p0, V0p1, V1p0, V1p1, V2p0, V2p1;
    V0p0 = pk(W2[0*10+u0i], W2[0*10+u0i+1]);  V0p1 = pk(W2[0*10+u0i+2], W2[0*10+u0i+3]);
    V1p0 = pk(W2[1*10+u0i], W2[1*10+u0i+1]);  V1p1 = pk(W2[1*10+u0i+2], W2[1*10+u0i+3]);
    V2p0 = pk(W2[2*10+u0i], W2[2*10+u0i+1]);  V2p1 = pk(W2[2*10+u0i+2], W2[2*10+u0i+3]);
    const float v0s = W2[0*10+j4], v1s = W2[1*10+j4], v2s = W2[2*10+j4];
    const float c20h = h ? 0.f : b2[0];
    const float c21h = h ? 0.f : b2[1];
    const float c22h = h ? 0.f : b2[2];

    // x for pair jg at t: 4 floats at runs[r][t][4*jg] (both lanes load same addr)
    const float* xb = runs + (size_t)r * T_STEPS * N_AGENTS * 2 + (size_t)jg * 4;

    float4 xq[PF];
#pragma unroll
    for (int d = 0; d < PF; ++d) {
        int tc = d - jg;
        tc = max(0, min(T_STEPS - 1, tc));
        xq[d] = *(const float4*)(xb + (size_t)tc * (N_AGENTS * 2));
    }
    const float* pf;
    {
        int tc = PF - jg;
        tc = max(0, min(T_STEPS - 1, tc));
        pf = xb + (size_t)tc * (N_AGENTS * 2);
    }

    // output: controls at out[r][t][2*jg], float2, stored by h==0 lanes only
    float* optr = out + (size_t)r * T_STEPS * N_AGENTS + (size_t)2 * jg
                      + (long long)(-jg) * N_AGENTS;
    int t = -jg;

    float o1Bp = 0.f;   // own pair's B.o1 from prev phase (full value, both lanes)
    float aSel = 0.f;   // resolved a-input for A

    __syncthreads();    // slots initialized

#pragma unroll 1
    for (int pb = 0; pb < NPHASE; pb += 3) {
        PHASE_ITER(0);
        PHASE_ITER(1);
        PHASE_ITER(2);
    }
}

extern "C" void kernel_launch(void* const* d_in, const int* in_sizes, int n_in,
                              void* d_out, int out_size)
{
    const float* runs = (const float*)d_in[0];
    const float* W1   = (const float*)d_in[1];
    const float* b1   = (const float*)d_in[2];
    const float* W2   = (const float*)d_in[3];
    const float* b2   = (const float*)d_in[4];
    float* out = (float*)d_out;
    com2net_4wsplit<<<R_RUNS, 128>>>(runs, W1, b1, W2, b2, out);
}